// round 1
// baseline (speedup 1.0000x reference)
#include <cuda_runtime.h>
#include <math.h>

// Problem constants
#define Bb 8
#define Tt 2048
#define Cc 1024
#define Hh 16
#define Nn 64
#define Mrows (Bb*Tt)          // 16384
#define BTC (Bb*Tt*Cc)         // 16777216

// ---------------- scratch (device globals; no allocation allowed) -------------
__device__ float g_R [BTC];
__device__ float g_K [BTC];   // becomes K2 in-place after kk_kernel
__device__ float g_V [BTC];   // updated in-place by vmix epilogue
__device__ float g_A [BTC];
__device__ float g_G [BTC];
__device__ float g_WD[BTC];   // exp(-exp(w))
__device__ float g_KK[BTC];
__device__ float g_Y [BTC];
__device__ float g_YG[BTC];
__device__ float g_HD[Mrows*64];
__device__ float g_HA[Mrows*64];
__device__ float g_HG[Mrows*128];
__device__ float g_HV[Mrows*32];

__device__ __forceinline__ float sigm(float x){ return 1.0f/(1.0f+expf(-x)); }

// ============================================================================
// Main GEMM: C[M,N] = A[M,K] @ B[K,N], 128x128 tile, BK=8, 256 thr, 8x8 micro.
// MIX: A is formed on the fly as x + (shift(x)-x)*maa  (time-mix).
// epi: 0 none; 1 decay: exp(-sigmoid(bias+v)*e^-0.5); 2 sigmoid(bias+v);
//      3 vmix: C = C + (vaux - C)*sigmoid(bias+v)   (C preloaded with V)
// ============================================================================
template<bool MIX>
__global__ void __launch_bounds__(256) gemm_f32(
    const float* __restrict__ A, const float* __restrict__ maa,
    const float* __restrict__ Bm, float* __restrict__ Cm,
    int M, int N, int K,
    int epi, const float* __restrict__ bias, const float* __restrict__ vaux)
{
    __shared__ float As[8][128];
    __shared__ float Bs[8][128];
    const int tid  = threadIdx.x;
    const int bm   = blockIdx.y, bn = blockIdx.x;
    const int arow = tid >> 1;
    const int acol = (tid & 1) << 2;
    const int brow = tid >> 5;
    const int bcol = (tid & 31) << 2;
    const int m    = bm*128 + arow;
    const int tr   = tid >> 4, tc = tid & 15;

    float acc[8][8] = {};

    const float* Aptr = A + (long)m*K + acol;
    for (int k0 = 0; k0 < K; k0 += 8) {
        float4 av = *(const float4*)(Aptr + k0);
        if (MIX) {
            float4 mv = *(const float4*)(maa + k0 + acol);
            float4 pv = make_float4(0.f,0.f,0.f,0.f);
            if ((m & (Tt-1)) != 0)           // t > 0 : previous timestep row
                pv = *(const float4*)(Aptr + k0 - Cc);
            av.x += (pv.x-av.x)*mv.x; av.y += (pv.y-av.y)*mv.y;
            av.z += (pv.z-av.z)*mv.z; av.w += (pv.w-av.w)*mv.w;
        }
        As[acol+0][arow]=av.x; As[acol+1][arow]=av.y;
        As[acol+2][arow]=av.z; As[acol+3][arow]=av.w;
        *(float4*)&Bs[brow][bcol] =
            *(const float4*)(Bm + (long)(k0+brow)*N + bn*128 + bcol);
        __syncthreads();
        #pragma unroll
        for (int kk = 0; kk < 8; kk++) {
            float af[8], bf[8];
            *(float4*)(af  ) = *(const float4*)&As[kk][tr*8  ];
            *(float4*)(af+4) = *(const float4*)&As[kk][tr*8+4];
            *(float4*)(bf  ) = *(const float4*)&Bs[kk][tc*8  ];
            *(float4*)(bf+4) = *(const float4*)&Bs[kk][tc*8+4];
            #pragma unroll
            for (int i = 0; i < 8; i++)
                #pragma unroll
                for (int j = 0; j < 8; j++)
                    acc[i][j] = fmaf(af[i], bf[j], acc[i][j]);
        }
        __syncthreads();
    }

    #pragma unroll
    for (int i = 0; i < 8; i++) {
        int row = bm*128 + tr*8 + i;
        #pragma unroll
        for (int j = 0; j < 8; j++) {
            int col = bn*128 + tc*8 + j;
            long idx = (long)row*N + col;
            float v = acc[i][j];
            if (epi == 1)      v = expf(-sigm(bias[col]+v)*0.60653065971263342f);
            else if (epi == 2) v = sigm(bias[col]+v);
            else if (epi == 3) {
                float s  = sigm(bias[col]+v);
                float vv = Cm[idx];
                v = vv + (vaux[idx]-vv)*s;
            }
            Cm[idx] = v;
        }
    }
}

// ============================================================================
// Small-N GEMM (N = 16*TN in {32,64,128}), K=1024, A always time-mixed.
// act: 0 none, 1 tanh, 2 sigmoid
// ============================================================================
template<int TN>
__global__ void __launch_bounds__(256) gemm_small(
    const float* __restrict__ X, const float* __restrict__ maa,
    const float* __restrict__ Bm, float* __restrict__ Cm,
    int K, int act)
{
    const int N = 16*TN;
    __shared__ float As[16][128];
    __shared__ float Bs[16][16*TN];
    const int tid  = threadIdx.x;
    const int bm   = blockIdx.x;
    const int arow = tid >> 1;
    const int acol = (tid & 1) << 3;
    const int m    = bm*128 + arow;
    const int tr   = tid >> 4, tc = tid & 15;

    float acc[8][TN] = {};
    const float* Xp = X + (long)m*K;

    for (int k0 = 0; k0 < K; k0 += 16) {
        #pragma unroll
        for (int h = 0; h < 8; h += 4) {
            int kc = acol + h;
            float4 av = *(const float4*)(Xp + k0 + kc);
            float4 mv = *(const float4*)(maa + k0 + kc);
            float4 pv = make_float4(0.f,0.f,0.f,0.f);
            if ((m & (Tt-1)) != 0)
                pv = *(const float4*)(Xp + k0 + kc - Cc);
            av.x += (pv.x-av.x)*mv.x; av.y += (pv.y-av.y)*mv.y;
            av.z += (pv.z-av.z)*mv.z; av.w += (pv.w-av.w)*mv.w;
            As[kc+0][arow]=av.x; As[kc+1][arow]=av.y;
            As[kc+2][arow]=av.z; As[kc+3][arow]=av.w;
        }
        #pragma unroll
        for (int q = 0; q < TN; q++) {
            int e = tid + 256*q;
            int r = e / N, c2 = e % N;
            Bs[r][c2] = Bm[(long)(k0+r)*N + c2];
        }
        __syncthreads();
        #pragma unroll
        for (int kk = 0; kk < 16; kk++) {
            float af[8];
            *(float4*)(af  ) = *(const float4*)&As[kk][tr*8  ];
            *(float4*)(af+4) = *(const float4*)&As[kk][tr*8+4];
            float bf[TN];
            #pragma unroll
            for (int j = 0; j < TN; j++) bf[j] = Bs[kk][tc*TN+j];
            #pragma unroll
            for (int i = 0; i < 8; i++)
                #pragma unroll
                for (int j = 0; j < TN; j++)
                    acc[i][j] = fmaf(af[i], bf[j], acc[i][j]);
        }
        __syncthreads();
    }

    #pragma unroll
    for (int i = 0; i < 8; i++)
        #pragma unroll
        for (int j = 0; j < TN; j++) {
            float v = acc[i][j];
            if (act == 1)      v = tanhf(v);
            else if (act == 2) v = sigm(v);
            Cm[(long)(bm*128 + tr*8 + i)*N + tc*TN + j] = v;
        }
}

// ============================================================================
// kk normalize + k update. One warp per head (lane handles 2 channels).
// KK = (k*misc_kkk)/max(||.||,1e-12);  K2 = k*(1+(a-1)*misc_a)  (in-place)
// ============================================================================
__global__ void kk_kernel(const float* __restrict__ Kin, const float* __restrict__ Aa,
                          const float* __restrict__ mkk, const float* __restrict__ ma,
                          float* __restrict__ KKo, float* __restrict__ K2o)
{
    int gw   = (blockIdx.x*blockDim.x + threadIdx.x) >> 5;
    int lane = threadIdx.x & 31;
    long off = (long)gw*64 + lane*2;
    int  c   = ((gw & (Hh-1))*64) + lane*2;
    float2 kv = *(const float2*)(Kin + off);
    float2 mk = *(const float2*)(mkk + c);
    float kk0 = kv.x*mk.x, kk1 = kv.y*mk.y;
    float ss = kk0*kk0 + kk1*kk1;
    #pragma unroll
    for (int s = 16; s > 0; s >>= 1) ss += __shfl_xor_sync(0xffffffffu, ss, s);
    float inv = 1.0f / fmaxf(sqrtf(ss), 1e-12f);
    *(float2*)(KKo + off) = make_float2(kk0*inv, kk1*inv);
    float2 av  = *(const float2*)(Aa + off);
    float2 mav = *(const float2*)(ma + c);
    *(float2*)(K2o + off) = make_float2(kv.x*(1.f+(av.x-1.f)*mav.x),
                                        kv.y*(1.f+(av.y-1.f)*mav.y));
}

// ============================================================================
// RWKV7 sequential scan. One CTA per (b,h); thread i owns state row i (64 regs).
// S[i][j] = S*w[j] - (S@kk)_i * (kk*a)[j] + v_i*k[j];  y_i = (S@r)_i
// Double-buffered shared staging of the 6 per-step vectors.
// ============================================================================
__global__ void __launch_bounds__(64) scan_kernel(
    const float* __restrict__ R,  const float* __restrict__ W,
    const float* __restrict__ K2, const float* __restrict__ V,
    const float* __restrict__ KK, const float* __restrict__ Aa,
    float* __restrict__ Y)
{
    const int bh = blockIdx.x;
    const int b  = bh >> 4, h = bh & 15;
    const int i  = threadIdx.x;
    const long base = (long)b*Tt*Cc + h*Nn + i;

    __shared__ __align__(16) float sm[2][6][Nn]; // 0:r 1:w 2:k 3:v 4:kk 5:bb

    float S[Nn];
    #pragma unroll
    for (int j = 0; j < Nn; j++) S[j] = 0.f;

    { // preload t=0
        long idx = base;
        sm[0][0][i]=R[idx]; sm[0][1][i]=W[idx]; sm[0][2][i]=K2[idx]; sm[0][3][i]=V[idx];
        float kki = KK[idx], ai = Aa[idx];
        sm[0][4][i]=kki; sm[0][5][i]=kki*ai;
    }
    __syncthreads();

    int p = 0;
    for (int t = 0; t < Tt; t++) {
        if (t + 1 < Tt) {
            long idx = base + (long)(t+1)*Cc;
            int q = p ^ 1;
            sm[q][0][i]=R[idx]; sm[q][1][i]=W[idx]; sm[q][2][i]=K2[idx]; sm[q][3][i]=V[idx];
            float kki = KK[idx], ai = Aa[idx];
            sm[q][4][i]=kki; sm[q][5][i]=kki*ai;
        }
        const float* rv  = sm[p][0];
        const float* wv  = sm[p][1];
        const float* kv  = sm[p][2];
        const float* kkv = sm[p][4];
        const float* bbv = sm[p][5];
        const float  vi  = sm[p][3][i];

        float sa0 = 0.f, sa1 = 0.f;
        #pragma unroll
        for (int j = 0; j < Nn; j += 4) {
            float4 u = *(const float4*)&kkv[j];
            sa0 = fmaf(S[j  ], u.x, sa0);
            sa1 = fmaf(S[j+1], u.y, sa1);
            sa0 = fmaf(S[j+2], u.z, sa0);
            sa1 = fmaf(S[j+3], u.w, sa1);
        }
        float sa = -(sa0 + sa1);

        float o0 = 0.f, o1 = 0.f;
        #pragma unroll
        for (int j = 0; j < Nn; j += 4) {
            float4 w4 = *(const float4*)&wv[j];
            float4 b4 = *(const float4*)&bbv[j];
            float4 k4 = *(const float4*)&kv[j];
            float4 r4 = *(const float4*)&rv[j];
            S[j  ] = fmaf(S[j  ], w4.x, fmaf(sa, b4.x, vi*k4.x));
            S[j+1] = fmaf(S[j+1], w4.y, fmaf(sa, b4.y, vi*k4.y));
            S[j+2] = fmaf(S[j+2], w4.z, fmaf(sa, b4.z, vi*k4.z));
            S[j+3] = fmaf(S[j+3], w4.w, fmaf(sa, b4.w, vi*k4.w));
            o0 = fmaf(S[j  ], r4.x, o0);
            o1 = fmaf(S[j+1], r4.y, o1);
            o0 = fmaf(S[j+2], r4.z, o0);
            o1 = fmaf(S[j+3], r4.w, o1);
        }
        Y[base + (long)t*Cc] = o0 + o1;
        __syncthreads();
        p ^= 1;
    }
}

// ============================================================================
// GroupNorm (per head) + rkv bonus + gate. One warp per head.
// ============================================================================
__global__ void post_kernel(const float* __restrict__ Y,  const float* __restrict__ R,
                            const float* __restrict__ K2, const float* __restrict__ V,
                            const float* __restrict__ G,  const float* __restrict__ faaaa,
                            const float* __restrict__ lnw,const float* __restrict__ lnb,
                            float* __restrict__ Out)
{
    int gw   = (blockIdx.x*blockDim.x + threadIdx.x) >> 5;
    int lane = threadIdx.x & 31;
    long off = (long)gw*64 + lane*2;
    int  c   = ((gw & 15)*64) + lane*2;
    float2 y  = *(const float2*)(Y + off);
    float2 r  = *(const float2*)(R + off);
    float2 k  = *(const float2*)(K2 + off);
    float2 fa = *(const float2*)(faaaa + c);
    float s1 = y.x + y.y;
    float s2 = y.x*y.x + y.y*y.y;
    float rk = r.x*k.x*fa.x + r.y*k.y*fa.y;
    #pragma unroll
    for (int s = 16; s > 0; s >>= 1) {
        s1 += __shfl_xor_sync(0xffffffffu, s1, s);
        s2 += __shfl_xor_sync(0xffffffffu, s2, s);
        rk += __shfl_xor_sync(0xffffffffu, rk, s);
    }
    float mu  = s1 * (1.0f/64.0f);
    float var = s2 * (1.0f/64.0f) - mu*mu;
    float rs  = rsqrtf(var + 6.4e-4f);   // eps = 1e-5 * 8^2
    float2 w2 = *(const float2*)(lnw + c);
    float2 b2 = *(const float2*)(lnb + c);
    float2 v  = *(const float2*)(V + off);
    float2 g  = *(const float2*)(G + off);
    float o0 = ((y.x-mu)*rs*w2.x + b2.x + rk*v.x) * g.x;
    float o1 = ((y.y-mu)*rs*w2.y + b2.y + rk*v.y) * g.y;
    *(float2*)(Out + off) = make_float2(o0, o1);
}

__global__ void copy_kernel(const float* __restrict__ src, float* __restrict__ dst, int n4)
{
    int idx = blockIdx.x*blockDim.x + threadIdx.x;
    if (idx < n4) ((float4*)dst)[idx] = ((const float4*)src)[idx];
}

// ============================================================================
extern "C" void kernel_launch(void* const* d_in, const int* in_sizes, int n_in,
                              void* d_out, int out_size)
{
    const float* x        = (const float*)d_in[0];
    const float* v0       = (const float*)d_in[1];
    const float* maa_r    = (const float*)d_in[2];
    const float* maa_w    = (const float*)d_in[3];
    const float* maa_k    = (const float*)d_in[4];
    const float* maa_v    = (const float*)d_in[5];
    const float* maa_a    = (const float*)d_in[6];
    const float* maa_g    = (const float*)d_in[7];
    const float* tdecay   = (const float*)d_in[8];
    const float* faaaa    = (const float*)d_in[9];
    const float* taaaaa   = (const float*)d_in[10];
    const float* decay_w1 = (const float*)d_in[11];
    const float* decay_w2 = (const float*)d_in[12];
    const float* aaa_w1   = (const float*)d_in[13];
    const float* aaa_w2   = (const float*)d_in[14];
    const float* gate_w1  = (const float*)d_in[15];
    const float* gate_w2  = (const float*)d_in[16];
    const float* mv_w1    = (const float*)d_in[17];
    const float* mv_w2    = (const float*)d_in[18];
    const float* misc_v   = (const float*)d_in[19];
    const float* misc_kkk = (const float*)d_in[20];
    const float* misc_a   = (const float*)d_in[21];
    const float* W_r      = (const float*)d_in[22];
    const float* W_k      = (const float*)d_in[23];
    const float* W_v      = (const float*)d_in[24];
    const float* W_out    = (const float*)d_in[25];
    const float* ln_w     = (const float*)d_in[26];
    const float* ln_b     = (const float*)d_in[27];

    static float *pR=nullptr,*pK,*pV,*pA,*pG,*pWD,*pKK,*pY,*pYG,*pHD,*pHA,*pHG,*pHV;
    if (!pR) {
        cudaGetSymbolAddress((void**)&pR,  g_R);
        cudaGetSymbolAddress((void**)&pK,  g_K);
        cudaGetSymbolAddress((void**)&pV,  g_V);
        cudaGetSymbolAddress((void**)&pA,  g_A);
        cudaGetSymbolAddress((void**)&pG,  g_G);
        cudaGetSymbolAddress((void**)&pWD, g_WD);
        cudaGetSymbolAddress((void**)&pKK, g_KK);
        cudaGetSymbolAddress((void**)&pY,  g_Y);
        cudaGetSymbolAddress((void**)&pYG, g_YG);
        cudaGetSymbolAddress((void**)&pHD, g_HD);
        cudaGetSymbolAddress((void**)&pHA, g_HA);
        cudaGetSymbolAddress((void**)&pHG, g_HG);
        cudaGetSymbolAddress((void**)&pHV, g_HV);
    }

    dim3 gBig(Cc/128, Mrows/128);   // (8, 128)

    // r/k/v projections (time-mix fused into A-load)
    gemm_f32<true><<<gBig,256>>>(x, maa_r, W_r, pR, Mrows, Cc, Cc, 0, nullptr, nullptr);
    gemm_f32<true><<<gBig,256>>>(x, maa_k, W_k, pK, Mrows, Cc, Cc, 0, nullptr, nullptr);
    gemm_f32<true><<<gBig,256>>>(x, maa_v, W_v, pV, Mrows, Cc, Cc, 0, nullptr, nullptr);

    // LoRA stage-1 (mix fused; activations: tanh / none / sigmoid / none)
    gemm_small<4><<<Mrows/128,256>>>(x, maa_w, decay_w1, pHD, Cc, 1);
    gemm_small<4><<<Mrows/128,256>>>(x, maa_a, aaa_w1,   pHA, Cc, 0);
    gemm_small<8><<<Mrows/128,256>>>(x, maa_g, gate_w1,  pHG, Cc, 2);
    gemm_small<2><<<Mrows/128,256>>>(x, maa_v, mv_w1,    pHV, Cc, 0);

    // LoRA stage-2 with fused epilogues
    gemm_f32<false><<<gBig,256>>>(pHD, nullptr, decay_w2, pWD, Mrows, Cc, 64,  1, tdecay, nullptr);
    gemm_f32<false><<<gBig,256>>>(pHA, nullptr, aaa_w2,   pA,  Mrows, Cc, 64,  2, taaaaa, nullptr);
    gemm_f32<false><<<gBig,256>>>(pHG, nullptr, gate_w2,  pG,  Mrows, Cc, 128, 0, nullptr, nullptr);
    gemm_f32<false><<<gBig,256>>>(pHV, nullptr, mv_w2,    pV,  Mrows, Cc, 32,  3, misc_v, v0);

    // kk normalize + k update (K -> K2 in place)
    kk_kernel<<<(Bb*Tt*Hh)/8, 256>>>(pK, pA, misc_kkk, misc_a, pKK, pK);

    // sequential RWKV7 recurrence
    scan_kernel<<<Bb*Hh, 64>>>(pR, pWD, pK, pV, pKK, pA, pY);

    // groupnorm + rkv bonus + gate
    post_kernel<<<(Bb*Tt*Hh)/8, 256>>>(pY, pR, pK, pV, pG, faaaa, ln_w, ln_b, pYG);

    // output projection straight into d_out
    gemm_f32<false><<<gBig,256>>>(pYG, nullptr, W_out, (float*)d_out, Mrows, Cc, Cc, 0, nullptr, nullptr);

    // second output of the tuple: v0 passthrough
    if (out_size >= 2*BTC)
        copy_kernel<<<(BTC/4 + 255)/256, 256>>>(v0, (float*)d_out + BTC, BTC/4);
}

// round 3
// speedup vs baseline: 1.4381x; 1.4381x over previous
#include <cuda_runtime.h>
#include <cuda_bf16.h>
#include <math.h>

// Problem constants
#define Bb 8
#define Tt 2048
#define Cc 1024
#define Hh 16
#define Nn 64
#define Mrows (Bb*Tt)          // 16384
#define BTC (Bb*Tt*Cc)         // 16777216

// ---------------- scratch (device globals; no allocation allowed) -------------
__device__ float g_R [BTC];
__device__ float g_K [BTC];   // becomes K2 in-place after kk_kernel
__device__ float g_V [BTC];   // updated in-place by vmix epilogue
__device__ float g_A [BTC];
__device__ float g_G [BTC];
__device__ float g_WD[BTC];   // exp(-exp(w))
__device__ float g_KK[BTC];
__device__ float g_Y [BTC];
__device__ float g_YG[BTC];
__device__ float g_HD[Mrows*64];
__device__ float g_HA[Mrows*64];
__device__ float g_HG[Mrows*128];
__device__ float g_HV[Mrows*32];

__device__ __forceinline__ float sigm(float x){ return 1.0f/(1.0f+expf(-x)); }

__device__ __forceinline__ void ldmat4(unsigned& r0, unsigned& r1, unsigned& r2, unsigned& r3,
                                       unsigned addr) {
    asm volatile("ldmatrix.sync.aligned.m8n8.x4.shared.b16 {%0,%1,%2,%3}, [%4];"
                 : "=r"(r0), "=r"(r1), "=r"(r2), "=r"(r3) : "r"(addr));
}
__device__ __forceinline__ void ldmat4t(unsigned& r0, unsigned& r1, unsigned& r2, unsigned& r3,
                                        unsigned addr) {
    asm volatile("ldmatrix.sync.aligned.m8n8.x4.trans.shared.b16 {%0,%1,%2,%3}, [%4];"
                 : "=r"(r0), "=r"(r1), "=r"(r2), "=r"(r3) : "r"(addr));
}
__device__ __forceinline__ void mma16816(float* c, const unsigned* a, unsigned b0, unsigned b1) {
    asm volatile("mma.sync.aligned.m16n8k16.row.col.f32.bf16.bf16.f32 "
                 "{%0,%1,%2,%3}, {%4,%5,%6,%7}, {%8,%9}, {%0,%1,%2,%3};"
                 : "+f"(c[0]), "+f"(c[1]), "+f"(c[2]), "+f"(c[3])
                 : "r"(a[0]), "r"(a[1]), "r"(a[2]), "r"(a[3]), "r"(b0), "r"(b1));
}

// ============================================================================
// Tensor-core GEMM: C[M,N] = A[M,K] @ B[K,N].
// bf16 hi/lo split (3 MMA passes) for ~fp32 precision; fp32 accumulate.
// CTA tile 128x128, BK=32, 8 warps (2Mx4N), warp tile 64x32, m16n8k16 atoms.
// MIX: A formed on the fly as x + (shift(x)-x)*maa (K==Cc in that case).
// epi: 0 none; 1 exp(-sigm(bias+v)*e^-.5); 2 sigm(bias+v);
//      3 vmix C=C+(vaux-C)*sigm(bias+v); 4 tanh(v); 5 sigm(v)
// ============================================================================
#define AST 40    // As row stride (bf16 elems), conflict-free for ldmatrix
#define BST 136   // Bs row stride

template<bool MIX>
__global__ void __launch_bounds__(256) gemm_mma(
    const float* __restrict__ A, const float* __restrict__ maa,
    const float* __restrict__ Bm, float* __restrict__ Cm,
    int N, int K, int epi,
    const float* __restrict__ bias, const float* __restrict__ vaux)
{
    __shared__ __nv_bfloat16 AsH[128*AST], AsL[128*AST];
    __shared__ __nv_bfloat16 BsH[32*BST],  BsL[32*BST];

    const int tid  = threadIdx.x;
    const int bm   = blockIdx.y, bn = blockIdx.x;
    const int warp = tid >> 5, lane = tid & 31;
    const int wm   = warp & 1,  wn  = warp >> 1;

    const int arow = tid >> 1, acol = (tid & 1) << 4;
    const int brow = tid >> 3, bcol = (tid & 7) << 4;
    const int m    = bm*128 + arow;

    float a_st[16], p_st[16], b_st[16];
    const float* Ap = A + (long)m*K + acol;

    float Cacc[4][4][4];
    #pragma unroll
    for (int i = 0; i < 4; i++)
        #pragma unroll
        for (int j = 0; j < 4; j++)
            #pragma unroll
            for (int e = 0; e < 4; e++) Cacc[i][j][e] = 0.f;

    // frag base offsets (bytes into smem arrays)
    const int aRow  = wm*64 + (lane & 7) + ((lane >> 3) & 1)*8;
    const int aCsel = (lane >> 4)*8;
    const unsigned aBaseH = (unsigned)__cvta_generic_to_shared(AsH) + (aRow*AST + aCsel)*2;
    const unsigned aBaseL = (unsigned)__cvta_generic_to_shared(AsL) + (aRow*AST + aCsel)*2;
    const int bKrow = ((lane >> 3) & 1)*8 + (lane & 7);
    const int bNcol = wn*32 + (lane >> 4)*8;
    const unsigned bBaseH = (unsigned)__cvta_generic_to_shared(BsH) + (bKrow*BST + bNcol)*2;
    const unsigned bBaseL = (unsigned)__cvta_generic_to_shared(BsL) + (bKrow*BST + bNcol)*2;

    // ---- prologue load (k0 = 0) ----
    {
        #pragma unroll
        for (int u = 0; u < 4; u++)
            *(float4*)(a_st + u*4) = *(const float4*)(Ap + u*4);
        if (MIX) {
            if ((m & (Tt-1)) != 0) {
                #pragma unroll
                for (int u = 0; u < 4; u++)
                    *(float4*)(p_st + u*4) = *(const float4*)(Ap + u*4 - Cc);
            } else {
                #pragma unroll
                for (int e = 0; e < 16; e++) p_st[e] = 0.f;
            }
        }
        #pragma unroll
        for (int u = 0; u < 4; u++) {
            int col = bn*128 + bcol + u*4;
            if (col < N)
                *(float4*)(b_st + u*4) = *(const float4*)(Bm + (long)brow*N + col);
            else
                *(float4*)(b_st + u*4) = make_float4(0.f,0.f,0.f,0.f);
        }
    }

    for (int k0 = 0; k0 < K; ) {
        __syncthreads();
        // ---- store stage: mix + bf16 split -> smem ----
        #pragma unroll
        for (int e = 0; e < 16; e += 2) {
            float v0 = a_st[e], v1 = a_st[e+1];
            if (MIX) {
                float m0 = maa[k0 + acol + e], m1 = maa[k0 + acol + e + 1];
                v0 += (p_st[e]   - v0)*m0;
                v1 += (p_st[e+1] - v1)*m1;
            }
            __nv_bfloat16 h0 = __float2bfloat16(v0), h1 = __float2bfloat16(v1);
            __nv_bfloat16 l0 = __float2bfloat16(v0 - __bfloat162float(h0));
            __nv_bfloat16 l1 = __float2bfloat16(v1 - __bfloat162float(h1));
            *(__nv_bfloat162*)&AsH[arow*AST + acol + e] = __nv_bfloat162(h0, h1);
            *(__nv_bfloat162*)&AsL[arow*AST + acol + e] = __nv_bfloat162(l0, l1);
        }
        #pragma unroll
        for (int e = 0; e < 16; e += 2) {
            float v0 = b_st[e], v1 = b_st[e+1];
            __nv_bfloat16 h0 = __float2bfloat16(v0), h1 = __float2bfloat16(v1);
            __nv_bfloat16 l0 = __float2bfloat16(v0 - __bfloat162float(h0));
            __nv_bfloat16 l1 = __float2bfloat16(v1 - __bfloat162float(h1));
            *(__nv_bfloat162*)&BsH[brow*BST + bcol + e] = __nv_bfloat162(h0, h1);
            *(__nv_bfloat162*)&BsL[brow*BST + bcol + e] = __nv_bfloat162(l0, l1);
        }
        __syncthreads();

        int kn = k0 + 32;
        // ---- prefetch next tile into registers ----
        if (kn < K) {
            #pragma unroll
            for (int u = 0; u < 4; u++)
                *(float4*)(a_st + u*4) = *(const float4*)(Ap + kn + u*4);
            if (MIX) {
                if ((m & (Tt-1)) != 0) {
                    #pragma unroll
                    for (int u = 0; u < 4; u++)
                        *(float4*)(p_st + u*4) = *(const float4*)(Ap + kn + u*4 - Cc);
                } else {
                    #pragma unroll
                    for (int e = 0; e < 16; e++) p_st[e] = 0.f;
                }
            }
            #pragma unroll
            for (int u = 0; u < 4; u++) {
                int col = bn*128 + bcol + u*4;
                if (col < N)
                    *(float4*)(b_st + u*4) = *(const float4*)(Bm + (long)(kn+brow)*N + col);
                else
                    *(float4*)(b_st + u*4) = make_float4(0.f,0.f,0.f,0.f);
            }
        }

        // ---- compute 2 k-steps of 16 ----
        #pragma unroll
        for (int ks = 0; ks < 2; ks++) {
            unsigned ah[4][4], al[4][4], bh[2][4], bl[2][4];
            #pragma unroll
            for (int i = 0; i < 4; i++) {
                unsigned off = (unsigned)(i*16*AST + ks*16)*2;
                ldmat4(ah[i][0], ah[i][1], ah[i][2], ah[i][3], aBaseH + off);
                ldmat4(al[i][0], al[i][1], al[i][2], al[i][3], aBaseL + off);
            }
            #pragma unroll
            for (int jj = 0; jj < 2; jj++) {
                unsigned off = (unsigned)(ks*16*BST + jj*16)*2;
                ldmat4t(bh[jj][0], bh[jj][1], bh[jj][2], bh[jj][3], bBaseH + off);
                ldmat4t(bl[jj][0], bl[jj][1], bl[jj][2], bl[jj][3], bBaseL + off);
            }
            #pragma unroll
            for (int i = 0; i < 4; i++)
                #pragma unroll
                for (int j = 0; j < 4; j++) {
                    int jj = j >> 1, sel = (j & 1)*2;
                    mma16816(Cacc[i][j], ah[i], bh[jj][sel],   bh[jj][sel+1]);
                    mma16816(Cacc[i][j], ah[i], bl[jj][sel],   bl[jj][sel+1]);
                    mma16816(Cacc[i][j], al[i], bh[jj][sel],   bh[jj][sel+1]);
                }
        }
        k0 = kn;
    }

    // ---- epilogue ----
    const int g = lane >> 2, q = lane & 3;
    #pragma unroll
    for (int i = 0; i < 4; i++) {
        int r0 = bm*128 + wm*64 + i*16 + g;
        #pragma unroll
        for (int j = 0; j < 4; j++) {
            int col = bn*128 + wn*32 + j*8 + q*2;
            if (col >= N) continue;
            #pragma unroll
            for (int h = 0; h < 2; h++) {
                int row = r0 + h*8;
                long idx = (long)row*N + col;
                float v0 = Cacc[i][j][h*2], v1 = Cacc[i][j][h*2+1];
                if (epi == 1) {
                    v0 = expf(-sigm(bias[col]  +v0)*0.60653065971263342f);
                    v1 = expf(-sigm(bias[col+1]+v1)*0.60653065971263342f);
                } else if (epi == 2) {
                    v0 = sigm(bias[col]+v0); v1 = sigm(bias[col+1]+v1);
                } else if (epi == 3) {
                    float s0 = sigm(bias[col]+v0), s1 = sigm(bias[col+1]+v1);
                    float c0 = Cm[idx], c1 = Cm[idx+1];
                    v0 = c0 + (vaux[idx]  -c0)*s0;
                    v1 = c1 + (vaux[idx+1]-c1)*s1;
                } else if (epi == 4) {
                    v0 = tanhf(v0); v1 = tanhf(v1);
                } else if (epi == 5) {
                    v0 = sigm(v0); v1 = sigm(v1);
                }
                *(float2*)&Cm[idx] = make_float2(v0, v1);
            }
        }
    }
}

// ============================================================================
// kk normalize + k update. One warp per head (lane handles 2 channels).
// ============================================================================
__global__ void kk_kernel(const float* __restrict__ Kin, const float* __restrict__ Aa,
                          const float* __restrict__ mkk, const float* __restrict__ ma,
                          float* __restrict__ KKo, float* __restrict__ K2o)
{
    int gw   = (blockIdx.x*blockDim.x + threadIdx.x) >> 5;
    int lane = threadIdx.x & 31;
    long off = (long)gw*64 + lane*2;
    int  c   = ((gw & (Hh-1))*64) + lane*2;
    float2 kv = *(const float2*)(Kin + off);
    float2 mk = *(const float2*)(mkk + c);
    float kk0 = kv.x*mk.x, kk1 = kv.y*mk.y;
    float ss = kk0*kk0 + kk1*kk1;
    #pragma unroll
    for (int s = 16; s > 0; s >>= 1) ss += __shfl_xor_sync(0xffffffffu, ss, s);
    float inv = 1.0f / fmaxf(sqrtf(ss), 1e-12f);
    *(float2*)(KKo + off) = make_float2(kk0*inv, kk1*inv);
    float2 av  = *(const float2*)(Aa + off);
    float2 mav = *(const float2*)(ma + c);
    *(float2*)(K2o + off) = make_float2(kv.x*(1.f+(av.x-1.f)*mav.x),
                                        kv.y*(1.f+(av.y-1.f)*mav.y));
}

// ============================================================================
// RWKV7 sequential scan. One CTA per (b,h); thread i owns state row i.
// ============================================================================
__global__ void __launch_bounds__(64) scan_kernel(
    const float* __restrict__ R,  const float* __restrict__ W,
    const float* __restrict__ K2, const float* __restrict__ V,
    const float* __restrict__ KK, const float* __restrict__ Aa,
    float* __restrict__ Y)
{
    const int bh = blockIdx.x;
    const int b  = bh >> 4, h = bh & 15;
    const int i  = threadIdx.x;
    const long base = (long)b*Tt*Cc + h*Nn + i;

    __shared__ __align__(16) float sm[2][6][Nn]; // 0:r 1:w 2:k 3:v 4:kk 5:bb

    float S[Nn];
    #pragma unroll
    for (int j = 0; j < Nn; j++) S[j] = 0.f;

    {
        long idx = base;
        sm[0][0][i]=R[idx]; sm[0][1][i]=W[idx]; sm[0][2][i]=K2[idx]; sm[0][3][i]=V[idx];
        float kki = KK[idx], ai = Aa[idx];
        sm[0][4][i]=kki; sm[0][5][i]=kki*ai;
    }
    __syncthreads();

    int p = 0;
    for (int t = 0; t < Tt; t++) {
        if (t + 1 < Tt) {
            long idx = base + (long)(t+1)*Cc;
            int q = p ^ 1;
            sm[q][0][i]=R[idx]; sm[q][1][i]=W[idx]; sm[q][2][i]=K2[idx]; sm[q][3][i]=V[idx];
            float kki = KK[idx], ai = Aa[idx];
            sm[q][4][i]=kki; sm[q][5][i]=kki*ai;
        }
        const float* rv  = sm[p][0];
        const float* wv  = sm[p][1];
        const float* kv  = sm[p][2];
        const float* kkv = sm[p][4];
        const float* bbv = sm[p][5];
        const float  vi  = sm[p][3][i];

        float sa0 = 0.f, sa1 = 0.f;
        #pragma unroll
        for (int j = 0; j < Nn; j += 4) {
            float4 u = *(const float4*)&kkv[j];
            sa0 = fmaf(S[j  ], u.x, sa0);
            sa1 = fmaf(S[j+1], u.y, sa1);
            sa0 = fmaf(S[j+2], u.z, sa0);
            sa1 = fmaf(S[j+3], u.w, sa1);
        }
        float sa = -(sa0 + sa1);

        float o0 = 0.f, o1 = 0.f;
        #pragma unroll
        for (int j = 0; j < Nn; j += 4) {
            float4 w4 = *(const float4*)&wv[j];
            float4 b4 = *(const float4*)&bbv[j];
            float4 k4 = *(const float4*)&kv[j];
            float4 r4 = *(const float4*)&rv[j];
            S[j  ] = fmaf(S[j  ], w4.x, fmaf(sa, b4.x, vi*k4.x));
            S[j+1] = fmaf(S[j+1], w4.y, fmaf(sa, b4.y, vi*k4.y));
            S[j+2] = fmaf(S[j+2], w4.z, fmaf(sa, b4.z, vi*k4.z));
            S[j+3] = fmaf(S[j+3], w4.w, fmaf(sa, b4.w, vi*k4.w));
            o0 = fmaf(S[j  ], r4.x, o0);
            o1 = fmaf(S[j+1], r4.y, o1);
            o0 = fmaf(S[j+2], r4.z, o0);
            o1 = fmaf(S[j+3], r4.w, o1);
        }
        Y[base + (long)t*Cc] = o0 + o1;
        __syncthreads();
        p ^= 1;
    }
}

// ============================================================================
// GroupNorm (per head) + rkv bonus + gate. One warp per head.
// ============================================================================
__global__ void post_kernel(const float* __restrict__ Y,  const float* __restrict__ R,
                            const float* __restrict__ K2, const float* __restrict__ V,
                            const float* __restrict__ G,  const float* __restrict__ faaaa,
                            const float* __restrict__ lnw,const float* __restrict__ lnb,
                            float* __restrict__ Out)
{
    int gw   = (blockIdx.x*blockDim.x + threadIdx.x) >> 5;
    int lane = threadIdx.x & 31;
    long off = (long)gw*64 + lane*2;
    int  c   = ((gw & 15)*64) + lane*2;
    float2 y  = *(const float2*)(Y + off);
    float2 r  = *(const float2*)(R + off);
    float2 k  = *(const float2*)(K2 + off);
    float2 fa = *(const float2*)(faaaa + c);
    float s1 = y.x + y.y;
    float s2 = y.x*y.x + y.y*y.y;
    float rk = r.x*k.x*fa.x + r.y*k.y*fa.y;
    #pragma unroll
    for (int s = 16; s > 0; s >>= 1) {
        s1 += __shfl_xor_sync(0xffffffffu, s1, s);
        s2 += __shfl_xor_sync(0xffffffffu, s2, s);
        rk += __shfl_xor_sync(0xffffffffu, rk, s);
    }
    float mu  = s1 * (1.0f/64.0f);
    float var = s2 * (1.0f/64.0f) - mu*mu;
    float rs  = rsqrtf(var + 6.4e-4f);   // eps = 1e-5 * 8^2
    float2 w2 = *(const float2*)(lnw + c);
    float2 b2 = *(const float2*)(lnb + c);
    float2 v  = *(const float2*)(V + off);
    float2 g  = *(const float2*)(G + off);
    float o0 = ((y.x-mu)*rs*w2.x + b2.x + rk*v.x) * g.x;
    float o1 = ((y.y-mu)*rs*w2.y + b2.y + rk*v.y) * g.y;
    *(float2*)(Out + off) = make_float2(o0, o1);
}

__global__ void copy_kernel(const float* __restrict__ src, float* __restrict__ dst, int n4)
{
    int idx = blockIdx.x*blockDim.x + threadIdx.x;
    if (idx < n4) ((float4*)dst)[idx] = ((const float4*)src)[idx];
}

// ============================================================================
extern "C" void kernel_launch(void* const* d_in, const int* in_sizes, int n_in,
                              void* d_out, int out_size)
{
    const float* x        = (const float*)d_in[0];
    const float* v0       = (const float*)d_in[1];
    const float* maa_r    = (const float*)d_in[2];
    const float* maa_w    = (const float*)d_in[3];
    const float* maa_k    = (const float*)d_in[4];
    const float* maa_v    = (const float*)d_in[5];
    const float* maa_a    = (const float*)d_in[6];
    const float* maa_g    = (const float*)d_in[7];
    const float* tdecay   = (const float*)d_in[8];
    const float* faaaa    = (const float*)d_in[9];
    const float* taaaaa   = (const float*)d_in[10];
    const float* decay_w1 = (const float*)d_in[11];
    const float* decay_w2 = (const float*)d_in[12];
    const float* aaa_w1   = (const float*)d_in[13];
    const float* aaa_w2   = (const float*)d_in[14];
    const float* gate_w1  = (const float*)d_in[15];
    const float* gate_w2  = (const float*)d_in[16];
    const float* mv_w1    = (const float*)d_in[17];
    const float* mv_w2    = (const float*)d_in[18];
    const float* misc_v   = (const float*)d_in[19];
    const float* misc_kkk = (const float*)d_in[20];
    const float* misc_a   = (const float*)d_in[21];
    const float* W_r      = (const float*)d_in[22];
    const float* W_k      = (const float*)d_in[23];
    const float* W_v      = (const float*)d_in[24];
    const float* W_out    = (const float*)d_in[25];
    const float* ln_w     = (const float*)d_in[26];
    const float* ln_b     = (const float*)d_in[27];

    static float *pR=nullptr,*pK,*pV,*pA,*pG,*pWD,*pKK,*pY,*pYG,*pHD,*pHA,*pHG,*pHV;
    if (!pR) {
        cudaGetSymbolAddress((void**)&pR,  g_R);
        cudaGetSymbolAddress((void**)&pK,  g_K);
        cudaGetSymbolAddress((void**)&pV,  g_V);
        cudaGetSymbolAddress((void**)&pA,  g_A);
        cudaGetSymbolAddress((void**)&pG,  g_G);
        cudaGetSymbolAddress((void**)&pWD, g_WD);
        cudaGetSymbolAddress((void**)&pKK, g_KK);
        cudaGetSymbolAddress((void**)&pY,  g_Y);
        cudaGetSymbolAddress((void**)&pYG, g_YG);
        cudaGetSymbolAddress((void**)&pHD, g_HD);
        cudaGetSymbolAddress((void**)&pHA, g_HA);
        cudaGetSymbolAddress((void**)&pHG, g_HG);
        cudaGetSymbolAddress((void**)&pHV, g_HV);
    }

    dim3 gBig(8, 128);     // N=1024
    dim3 gNar(1, 128);     // N<=128

    // r/k/v projections (time-mix fused into A-load)
    gemm_mma<true><<<gBig,256>>>(x, maa_r, W_r, pR, 1024, Cc, 0, nullptr, nullptr);
    gemm_mma<true><<<gBig,256>>>(x, maa_k, W_k, pK, 1024, Cc, 0, nullptr, nullptr);
    gemm_mma<true><<<gBig,256>>>(x, maa_v, W_v, pV, 1024, Cc, 0, nullptr, nullptr);

    // LoRA stage-1 (mix fused; activations: tanh / none / sigmoid / none)
    gemm_mma<true><<<gNar,256>>>(x, maa_w, decay_w1, pHD, 64,  Cc, 4, nullptr, nullptr);
    gemm_mma<true><<<gNar,256>>>(x, maa_a, aaa_w1,   pHA, 64,  Cc, 0, nullptr, nullptr);
    gemm_mma<true><<<gNar,256>>>(x, maa_g, gate_w1,  pHG, 128, Cc, 5, nullptr, nullptr);
    gemm_mma<true><<<gNar,256>>>(x, maa_v, mv_w1,    pHV, 32,  Cc, 0, nullptr, nullptr);

    // LoRA stage-2 with fused epilogues
    gemm_mma<false><<<gBig,256>>>(pHD, nullptr, decay_w2, pWD, 1024, 64,  1, tdecay, nullptr);
    gemm_mma<false><<<gBig,256>>>(pHA, nullptr, aaa_w2,   pA,  1024, 64,  2, taaaaa, nullptr);
    gemm_mma<false><<<gBig,256>>>(pHG, nullptr, gate_w2,  pG,  1024, 128, 0, nullptr, nullptr);
    gemm_mma<false><<<gBig,256>>>(pHV, nullptr, mv_w2,    pV,  1024, 32,  3, misc_v, v0);

    // kk normalize + k update (K -> K2 in place)
    kk_kernel<<<(Bb*Tt*Hh)/8, 256>>>(pK, pA, misc_kkk, misc_a, pKK, pK);

    // sequential RWKV7 recurrence
    scan_kernel<<<Bb*Hh, 64>>>(pR, pWD, pK, pV, pKK, pA, pY);

    // groupnorm + rkv bonus + gate
    post_kernel<<<(Bb*Tt*Hh)/8, 256>>>(pY, pR, pK, pV, pG, faaaa, ln_w, ln_b, pYG);

    // output projection straight into d_out
    gemm_mma<false><<<gBig,256>>>(pYG, nullptr, W_out, (float*)d_out, 1024, Cc, 0, nullptr, nullptr);

    // second output of the tuple: v0 passthrough
    if (out_size >= 2*BTC)
        copy_kernel<<<(BTC/4 + 255)/256, 256>>>(v0, (float*)d_out + BTC, BTC/4);
}

// round 4
// speedup vs baseline: 1.7342x; 1.2059x over previous
#include <cuda_runtime.h>
#include <cuda_bf16.h>
#include <math.h>

#define Bb 8
#define Tt 2048
#define Cc 1024
#define Hh 16
#define Nn 64
#define Mrows 16384
#define BTC 16777216

typedef __nv_bfloat16 bf16;

// ---------------- fp32 scratch ----------------
__device__ float g_R[BTC], g_K[BTC], g_V[BTC], g_A[BTC], g_G[BTC];
__device__ float g_WD[BTC], g_KK[BTC], g_Y[BTC];

// ---------------- bf16 hi/lo planes ----------------
__device__ __align__(256) bf16 g_XH[6l*BTC];     // 6 mixed x variants (r,w,k,v,a,g)
__device__ __align__(256) bf16 g_XL[6l*BTC];
__device__ __align__(256) bf16 g_WH[5242880];    // packed weights (padded)
__device__ __align__(256) bf16 g_WL[5242880];
__device__ __align__(256) bf16 g_HH[4l*Mrows*128]; // LoRA hidden states
__device__ __align__(256) bf16 g_HL[4l*Mrows*128];
__device__ __align__(256) bf16 g_YGH[BTC];       // post output
__device__ __align__(256) bf16 g_YGL[BTC];

// weight pack offsets (elements)
#define W_R  0
#define W_K  1048576
#define W_V  2097152
#define W_O  3145728
#define W_L(i) (4194304 + (i)*131072)   // i: 0 dw1,1 aw1,2 gw1,3 mw1,4 dw2,5 aw2,6 gw2,7 mw2

__device__ __forceinline__ float sigm(float x){ return 1.0f/(1.0f+expf(-x)); }
__device__ __forceinline__ void split2(float v, bf16& h, bf16& l){
    h = __float2bfloat16(v); l = __float2bfloat16(v - __bfloat162float(h));
}

__device__ __forceinline__ void ldmat4(unsigned& r0, unsigned& r1, unsigned& r2, unsigned& r3,
                                       unsigned addr) {
    asm volatile("ldmatrix.sync.aligned.m8n8.x4.shared.b16 {%0,%1,%2,%3}, [%4];"
                 : "=r"(r0), "=r"(r1), "=r"(r2), "=r"(r3) : "r"(addr));
}
__device__ __forceinline__ void ldmat4t(unsigned& r0, unsigned& r1, unsigned& r2, unsigned& r3,
                                        unsigned addr) {
    asm volatile("ldmatrix.sync.aligned.m8n8.x4.trans.shared.b16 {%0,%1,%2,%3}, [%4];"
                 : "=r"(r0), "=r"(r1), "=r"(r2), "=r"(r3) : "r"(addr));
}
__device__ __forceinline__ void mma16816(float* c, const unsigned* a, unsigned b0, unsigned b1) {
    asm volatile("mma.sync.aligned.m16n8k16.row.col.f32.bf16.bf16.f32 "
                 "{%0,%1,%2,%3}, {%4,%5,%6,%7}, {%8,%9}, {%0,%1,%2,%3};"
                 : "+f"(c[0]), "+f"(c[1]), "+f"(c[2]), "+f"(c[3])
                 : "r"(a[0]), "r"(a[1]), "r"(a[2]), "r"(a[3]), "r"(b0), "r"(b1));
}
__device__ __forceinline__ void cpa16(unsigned dst, const void* src) {
    asm volatile("cp.async.cg.shared.global [%0], [%1], 16;" :: "r"(dst), "l"(src));
}
__device__ __forceinline__ void cpcommit(){ asm volatile("cp.async.commit_group;"); }
__device__ __forceinline__ void cpwait1(){ asm volatile("cp.async.wait_group 1;"); }

// ============================================================================
// prep: mix x with 6 maa vectors, split to bf16 hi/lo planes.
// ============================================================================
__global__ void __launch_bounds__(256) prep_kernel(
    const float* __restrict__ x,
    const float* __restrict__ m0, const float* __restrict__ m1,
    const float* __restrict__ m2, const float* __restrict__ m3,
    const float* __restrict__ m4, const float* __restrict__ m5)
{
    long e = ((long)blockIdx.x*256 + threadIdx.x)*4;
    int r = (int)(e >> 10), c = (int)(e & 1023);
    float4 cur = *(const float4*)(x + e);
    float4 prv = make_float4(0.f,0.f,0.f,0.f);
    if ((r & (Tt-1)) != 0) prv = *(const float4*)(x + e - Cc);
    float d0 = prv.x-cur.x, d1 = prv.y-cur.y, d2 = prv.z-cur.z, d3 = prv.w-cur.w;
    const float* maas[6] = {m0,m1,m2,m3,m4,m5};
    #pragma unroll
    for (int v = 0; v < 6; v++) {
        float4 mv = *(const float4*)(maas[v] + c);
        float a0 = cur.x + d0*mv.x, a1 = cur.y + d1*mv.y;
        float a2 = cur.z + d2*mv.z, a3 = cur.w + d3*mv.w;
        bf16 h0,l0,h1,l1,h2,l2,h3,l3;
        split2(a0,h0,l0); split2(a1,h1,l1); split2(a2,h2,l2); split2(a3,h3,l3);
        long o = (long)v*BTC + e;
        *(__nv_bfloat162*)&g_XH[o]   = __nv_bfloat162(h0,h1);
        *(__nv_bfloat162*)&g_XH[o+2] = __nv_bfloat162(h2,h3);
        *(__nv_bfloat162*)&g_XL[o]   = __nv_bfloat162(l0,l1);
        *(__nv_bfloat162*)&g_XL[o+2] = __nv_bfloat162(l2,l3);
    }
}

// ============================================================================
// wsplit: split a [K,N] fp32 weight into padded [Kp,Np] bf16 hi/lo planes.
// ============================================================================
__global__ void wsplit_kernel(const float* __restrict__ src, int K, int N,
                              int Kp, int Np, long dstOff)
{
    int g = blockIdx.x*256 + threadIdx.x;
    if (g >= Kp*Np) return;
    int r = g / Np, c = g - r*Np;
    float v = (r < K && c < N) ? src[(long)r*N + c] : 0.f;
    bf16 h,l; split2(v,h,l);
    g_WH[dstOff + g] = h; g_WL[dstOff + g] = l;
}

// ============================================================================
// Pipelined bf16 GEMM: C[M,N] = A[M,K] @ B[K,N], hi/lo split 3-pass.
// CTA 128x128, BK=32, 3-stage cp.async, 8 warps (2Mx4N), warp 64x32.
// epi: 0 none; 1 exp(-sigm(bias+v)*e^-.5); 2 sigm(bias+v);
//      3 vmix C=C+(vaux-C)*sigm(bias+v); 4 tanh; 5 sigm
// outmode: 0 fp32 -> Cf; 1 bf16 hi/lo planes -> ChH/ChL
// ============================================================================
#define AST 40
#define BST 136
#define OFF_AL 5120
#define OFF_BH 10240
#define OFF_BL 14592
#define STAGE_E 18944
#define STAGE_B (STAGE_E*2)
#define SMEM_TOT (3*STAGE_B)

__global__ void __launch_bounds__(256) gemm_bf16(
    const bf16* __restrict__ Ah, const bf16* __restrict__ Al,
    const bf16* __restrict__ Bh, const bf16* __restrict__ Bl,
    int N, int K, int epi, const float* __restrict__ bias,
    int outmode, float* __restrict__ Cf,
    bf16* __restrict__ ChH, bf16* __restrict__ ChL,
    const float* __restrict__ vaux)
{
    extern __shared__ __align__(16) bf16 smem[];
    const unsigned smemU = (unsigned)__cvta_generic_to_shared(smem);

    const int tid  = threadIdx.x;
    const int bm   = blockIdx.y, bn = blockIdx.x;
    const int warp = tid >> 5, lane = tid & 31;
    const int wm   = warp & 1,  wn  = warp >> 1;

    // cp.async chunk coords
    const int ar = tid >> 2,            ac = (tid & 3)*8;     // +128 rows via u
    const int br = tid >> 4,            bc = (tid & 15)*8;    // +16 rows via u

    const long aRowBase = (long)(bm*128)*K;
    const long bColBase = (long)bn*128;

    float Cacc[4][4][4];
    #pragma unroll
    for (int i = 0; i < 4; i++)
        #pragma unroll
        for (int j = 0; j < 4; j++)
            #pragma unroll
            for (int e = 0; e < 4; e++) Cacc[i][j][e] = 0.f;

    const int aRow  = wm*64 + (lane & 7) + ((lane >> 3) & 1)*8;
    const int aCsel = (lane >> 4)*8;
    const int bKrow = ((lane >> 3) & 1)*8 + (lane & 7);
    const int bNcol = wn*32 + (lane >> 4)*8;

    const int NIT = K >> 5;

    auto issue = [&](int s, int k0) {
        unsigned sb = smemU + s*STAGE_B;
        #pragma unroll
        for (int u = 0; u < 2; u++) {
            int r  = ar + u*64;
            cpa16(sb + (r*AST + ac)*2,            Ah + aRowBase + (long)r*K + k0 + ac);
            cpa16(sb + (OFF_AL + r*AST + ac)*2,   Al + aRowBase + (long)r*K + k0 + ac);
            int r2 = br + u*16;
            cpa16(sb + (OFF_BH + r2*BST + bc)*2,  Bh + (long)(k0+r2)*N + bColBase + bc);
            cpa16(sb + (OFF_BL + r2*BST + bc)*2,  Bl + (long)(k0+r2)*N + bColBase + bc);
        }
        cpcommit();
    };

    issue(0, 0);
    if (NIT > 1) issue(1, 32); else cpcommit();

    for (int it = 0; it < NIT; it++) {
        cpwait1();
        __syncthreads();
        if (it + 2 < NIT) issue((it+2) % 3, (it+2)*32); else cpcommit();

        unsigned sb = smemU + (it % 3)*STAGE_B;
        unsigned aH = sb + (aRow*AST + aCsel)*2;
        unsigned aL = aH + OFF_AL*2;
        unsigned bH = sb + (OFF_BH + bKrow*BST + bNcol)*2;
        unsigned bL = bH + (OFF_BL-OFF_BH)*2;

        #pragma unroll
        for (int ks = 0; ks < 2; ks++) {
            unsigned ah[4][4], al[4][4], bh[2][4], bl[2][4];
            #pragma unroll
            for (int i = 0; i < 4; i++) {
                unsigned off = (unsigned)(i*16*AST + ks*16)*2;
                ldmat4(ah[i][0], ah[i][1], ah[i][2], ah[i][3], aH + off);
                ldmat4(al[i][0], al[i][1], al[i][2], al[i][3], aL + off);
            }
            #pragma unroll
            for (int jj = 0; jj < 2; jj++) {
                unsigned off = (unsigned)(ks*16*BST + jj*16)*2;
                ldmat4t(bh[jj][0], bh[jj][1], bh[jj][2], bh[jj][3], bH + off);
                ldmat4t(bl[jj][0], bl[jj][1], bl[jj][2], bl[jj][3], bL + off);
            }
            #pragma unroll
            for (int i = 0; i < 4; i++)
                #pragma unroll
                for (int j = 0; j < 4; j++) {
                    int jj = j >> 1, sel = (j & 1)*2;
                    mma16816(Cacc[i][j], ah[i], bh[jj][sel], bh[jj][sel+1]);
                    mma16816(Cacc[i][j], ah[i], bl[jj][sel], bl[jj][sel+1]);
                    mma16816(Cacc[i][j], al[i], bh[jj][sel], bh[jj][sel+1]);
                }
        }
        __syncthreads();
    }

    // ---- epilogue ----
    const int g = lane >> 2, q = lane & 3;
    #pragma unroll
    for (int i = 0; i < 4; i++) {
        int r0 = bm*128 + wm*64 + i*16 + g;
        #pragma unroll
        for (int j = 0; j < 4; j++) {
            int col = bn*128 + wn*32 + j*8 + q*2;
            #pragma unroll
            for (int h = 0; h < 2; h++) {
                int row = r0 + h*8;
                long idx = (long)row*N + col;
                float v0 = Cacc[i][j][h*2], v1 = Cacc[i][j][h*2+1];
                if (epi == 1) {
                    v0 = expf(-sigm(bias[col]  +v0)*0.60653065971263342f);
                    v1 = expf(-sigm(bias[col+1]+v1)*0.60653065971263342f);
                } else if (epi == 2) {
                    v0 = sigm(bias[col]+v0); v1 = sigm(bias[col+1]+v1);
                } else if (epi == 3) {
                    float s0 = sigm(bias[col]+v0), s1 = sigm(bias[col+1]+v1);
                    float c0 = Cf[idx], c1 = Cf[idx+1];
                    v0 = c0 + (vaux[idx]  -c0)*s0;
                    v1 = c1 + (vaux[idx+1]-c1)*s1;
                } else if (epi == 4) {
                    v0 = tanhf(v0); v1 = tanhf(v1);
                } else if (epi == 5) {
                    v0 = sigm(v0); v1 = sigm(v1);
                }
                if (outmode == 0) {
                    *(float2*)&Cf[idx] = make_float2(v0, v1);
                } else {
                    bf16 h0,l0,h1,l1;
                    split2(v0,h0,l0); split2(v1,h1,l1);
                    *(__nv_bfloat162*)&ChH[idx] = __nv_bfloat162(h0,h1);
                    *(__nv_bfloat162*)&ChL[idx] = __nv_bfloat162(l0,l1);
                }
            }
        }
    }
}

// ============================================================================
// kk normalize + k update. One warp per head (lane handles 2 channels).
// ============================================================================
__global__ void kk_kernel(const float* __restrict__ Kin, const float* __restrict__ Aa,
                          const float* __restrict__ mkk, const float* __restrict__ ma,
                          float* __restrict__ KKo, float* __restrict__ K2o)
{
    int gw   = (blockIdx.x*blockDim.x + threadIdx.x) >> 5;
    int lane = threadIdx.x & 31;
    long off = (long)gw*64 + lane*2;
    int  c   = ((gw & (Hh-1))*64) + lane*2;
    float2 kv = *(const float2*)(Kin + off);
    float2 mk = *(const float2*)(mkk + c);
    float kk0 = kv.x*mk.x, kk1 = kv.y*mk.y;
    float ss = kk0*kk0 + kk1*kk1;
    #pragma unroll
    for (int s = 16; s > 0; s >>= 1) ss += __shfl_xor_sync(0xffffffffu, ss, s);
    float inv = 1.0f / fmaxf(sqrtf(ss), 1e-12f);
    *(float2*)(KKo + off) = make_float2(kk0*inv, kk1*inv);
    float2 av  = *(const float2*)(Aa + off);
    float2 mav = *(const float2*)(ma + c);
    *(float2*)(K2o + off) = make_float2(kv.x*(1.f+(av.x-1.f)*mav.x),
                                        kv.y*(1.f+(av.y-1.f)*mav.y));
}

// ============================================================================
// RWKV7 scan: 128 threads per (b,h); thread owns half a state row (32 regs).
// Pair (tid, tid^1) covers one row; reduce via shfl_xor 1.
// ============================================================================
__global__ void __launch_bounds__(128) scan_kernel(
    const float* __restrict__ R,  const float* __restrict__ W,
    const float* __restrict__ K2, const float* __restrict__ V,
    const float* __restrict__ KK, const float* __restrict__ Aa,
    float* __restrict__ Y)
{
    const int bh = blockIdx.x;
    const int b  = bh >> 4, hh = bh & 15;
    const int tid  = threadIdx.x;
    const int i    = tid >> 1;
    const int half = tid & 1;
    const int cb   = half*32;
    const long rowbase = (long)b*Tt*Cc + hh*Nn;

    __shared__ __align__(16) float sm[2][6][Nn];

    float S[32];
    #pragma unroll
    for (int j = 0; j < 32; j++) S[j] = 0.f;

    // stage loader: 3 loads per thread
    auto loadstage = [&](int q, int t) {
        long idx = rowbase + (long)t*Cc;
        if (tid < 64) {
            sm[q][0][tid] = R[idx+tid];
            sm[q][1][tid] = W[idx+tid];
            sm[q][2][tid] = K2[idx+tid];
        } else {
            int j = tid - 64;
            sm[q][3][j] = V[idx+j];
            float kk = KK[idx+j], a = Aa[idx+j];
            sm[q][4][j] = kk; sm[q][5][j] = kk*a;
        }
    };

    loadstage(0, 0);
    __syncthreads();

    int p = 0;
    for (int t = 0; t < Tt; t++) {
        if (t + 1 < Tt) loadstage(p^1, t+1);
        const float* rv  = &sm[p][0][cb];
        const float* wv  = &sm[p][1][cb];
        const float* kv  = &sm[p][2][cb];
        const float* kkv = &sm[p][4][cb];
        const float* bbv = &sm[p][5][cb];
        const float  vi  = sm[p][3][i];

        float sa0 = 0.f, sa1 = 0.f;
        #pragma unroll
        for (int j = 0; j < 32; j += 4) {
            float4 u = *(const float4*)&kkv[j];
            sa0 = fmaf(S[j  ], u.x, sa0);
            sa1 = fmaf(S[j+1], u.y, sa1);
            sa0 = fmaf(S[j+2], u.z, sa0);
            sa1 = fmaf(S[j+3], u.w, sa1);
        }
        float sa_p = sa0 + sa1;
        float sa = -(sa_p + __shfl_xor_sync(0xffffffffu, sa_p, 1));

        float o0 = 0.f, o1 = 0.f;
        #pragma unroll
        for (int j = 0; j < 32; j += 4) {
            float4 w4 = *(const float4*)&wv[j];
            float4 b4 = *(const float4*)&bbv[j];
            float4 k4 = *(const float4*)&kv[j];
            float4 r4 = *(const float4*)&rv[j];
            S[j  ] = fmaf(S[j  ], w4.x, fmaf(sa, b4.x, vi*k4.x));
            S[j+1] = fmaf(S[j+1], w4.y, fmaf(sa, b4.y, vi*k4.y));
            S[j+2] = fmaf(S[j+2], w4.z, fmaf(sa, b4.z, vi*k4.z));
            S[j+3] = fmaf(S[j+3], w4.w, fmaf(sa, b4.w, vi*k4.w));
            o0 = fmaf(S[j  ], r4.x, o0);
            o1 = fmaf(S[j+1], r4.y, o1);
            o0 = fmaf(S[j+2], r4.z, o0);
            o1 = fmaf(S[j+3], r4.w, o1);
        }
        float o_p = o0 + o1;
        float o = o_p + __shfl_xor_sync(0xffffffffu, o_p, 1);
        if (half == 0) Y[rowbase + (long)t*Cc + i] = o;
        __syncthreads();
        p ^= 1;
    }
}

// ============================================================================
// GroupNorm + rkv bonus + gate -> bf16 hi/lo planes for the output GEMM.
// ============================================================================
__global__ void post_kernel(const float* __restrict__ Y,  const float* __restrict__ R,
                            const float* __restrict__ K2, const float* __restrict__ V,
                            const float* __restrict__ G,  const float* __restrict__ faaaa,
                            const float* __restrict__ lnw,const float* __restrict__ lnb)
{
    int gw   = (blockIdx.x*blockDim.x + threadIdx.x) >> 5;
    int lane = threadIdx.x & 31;
    long off = (long)gw*64 + lane*2;
    int  c   = ((gw & 15)*64) + lane*2;
    float2 y  = *(const float2*)(Y + off);
    float2 r  = *(const float2*)(R + off);
    float2 k  = *(const float2*)(K2 + off);
    float2 fa = *(const float2*)(faaaa + c);
    float s1 = y.x + y.y;
    float s2 = y.x*y.x + y.y*y.y;
    float rk = r.x*k.x*fa.x + r.y*k.y*fa.y;
    #pragma unroll
    for (int s = 16; s > 0; s >>= 1) {
        s1 += __shfl_xor_sync(0xffffffffu, s1, s);
        s2 += __shfl_xor_sync(0xffffffffu, s2, s);
        rk += __shfl_xor_sync(0xffffffffu, rk, s);
    }
    float mu  = s1 * (1.0f/64.0f);
    float var = s2 * (1.0f/64.0f) - mu*mu;
    float rs  = rsqrtf(var + 6.4e-4f);
    float2 w2 = *(const float2*)(lnw + c);
    float2 b2 = *(const float2*)(lnb + c);
    float2 v  = *(const float2*)(V + off);
    float2 g  = *(const float2*)(G + off);
    float o0 = ((y.x-mu)*rs*w2.x + b2.x + rk*v.x) * g.x;
    float o1 = ((y.y-mu)*rs*w2.y + b2.y + rk*v.y) * g.y;
    bf16 h0,l0,h1,l1;
    split2(o0,h0,l0); split2(o1,h1,l1);
    *(__nv_bfloat162*)&g_YGH[off] = __nv_bfloat162(h0,h1);
    *(__nv_bfloat162*)&g_YGL[off] = __nv_bfloat162(l0,l1);
}

__global__ void copy_kernel(const float* __restrict__ src, float* __restrict__ dst, int n4)
{
    int idx = blockIdx.x*blockDim.x + threadIdx.x;
    if (idx < n4) ((float4*)dst)[idx] = ((const float4*)src)[idx];
}

// ============================================================================
extern "C" void kernel_launch(void* const* d_in, const int* in_sizes, int n_in,
                              void* d_out, int out_size)
{
    const float* x        = (const float*)d_in[0];
    const float* v0       = (const float*)d_in[1];
    const float* maa_r    = (const float*)d_in[2];
    const float* maa_w    = (const float*)d_in[3];
    const float* maa_k    = (const float*)d_in[4];
    const float* maa_v    = (const float*)d_in[5];
    const float* maa_a    = (const float*)d_in[6];
    const float* maa_g    = (const float*)d_in[7];
    const float* tdecay   = (const float*)d_in[8];
    const float* faaaa    = (const float*)d_in[9];
    const float* taaaaa   = (const float*)d_in[10];
    const float* decay_w1 = (const float*)d_in[11];
    const float* decay_w2 = (const float*)d_in[12];
    const float* aaa_w1   = (const float*)d_in[13];
    const float* aaa_w2   = (const float*)d_in[14];
    const float* gate_w1  = (const float*)d_in[15];
    const float* gate_w2  = (const float*)d_in[16];
    const float* mv_w1    = (const float*)d_in[17];
    const float* mv_w2    = (const float*)d_in[18];
    const float* misc_v   = (const float*)d_in[19];
    const float* misc_kkk = (const float*)d_in[20];
    const float* misc_a   = (const float*)d_in[21];
    const float* W_r      = (const float*)d_in[22];
    const float* W_k      = (const float*)d_in[23];
    const float* W_v      = (const float*)d_in[24];
    const float* W_out    = (const float*)d_in[25];
    const float* ln_w     = (const float*)d_in[26];
    const float* ln_b     = (const float*)d_in[27];

    static float *pR=nullptr,*pK,*pV,*pA,*pG,*pWD,*pKK,*pY;
    static bf16 *pXH,*pXL,*pWH,*pWL,*pHH,*pHL,*pYGH,*pYGL;
    if (!pR) {
        cudaGetSymbolAddress((void**)&pR,  g_R);
        cudaGetSymbolAddress((void**)&pK,  g_K);
        cudaGetSymbolAddress((void**)&pV,  g_V);
        cudaGetSymbolAddress((void**)&pA,  g_A);
        cudaGetSymbolAddress((void**)&pG,  g_G);
        cudaGetSymbolAddress((void**)&pWD, g_WD);
        cudaGetSymbolAddress((void**)&pKK, g_KK);
        cudaGetSymbolAddress((void**)&pY,  g_Y);
        cudaGetSymbolAddress((void**)&pXH, g_XH);
        cudaGetSymbolAddress((void**)&pXL, g_XL);
        cudaGetSymbolAddress((void**)&pWH, g_WH);
        cudaGetSymbolAddress((void**)&pWL, g_WL);
        cudaGetSymbolAddress((void**)&pHH, g_HH);
        cudaGetSymbolAddress((void**)&pHL, g_HL);
        cudaGetSymbolAddress((void**)&pYGH, g_YGH);
        cudaGetSymbolAddress((void**)&pYGL, g_YGL);
        cudaFuncSetAttribute(gemm_bf16, cudaFuncAttributeMaxDynamicSharedMemorySize, SMEM_TOT);
    }

    // ---- operand preparation ----
    prep_kernel<<<BTC/1024, 256>>>(x, maa_r, maa_w, maa_k, maa_v, maa_a, maa_g);
    wsplit_kernel<<<(1048576+255)/256,256>>>(W_r,   1024,1024,1024,1024, W_R);
    wsplit_kernel<<<(1048576+255)/256,256>>>(W_k,   1024,1024,1024,1024, W_K);
    wsplit_kernel<<<(1048576+255)/256,256>>>(W_v,   1024,1024,1024,1024, W_V);
    wsplit_kernel<<<(1048576+255)/256,256>>>(W_out, 1024,1024,1024,1024, W_O);
    wsplit_kernel<<<(131072+255)/256,256>>>(decay_w1, 1024,64, 1024,128, W_L(0));
    wsplit_kernel<<<(131072+255)/256,256>>>(aaa_w1,   1024,64, 1024,128, W_L(1));
    wsplit_kernel<<<(131072+255)/256,256>>>(gate_w1,  1024,128,1024,128, W_L(2));
    wsplit_kernel<<<(131072+255)/256,256>>>(mv_w1,    1024,32, 1024,128, W_L(3));
    wsplit_kernel<<<(131072+255)/256,256>>>(decay_w2, 64, 1024,128,1024, W_L(4));
    wsplit_kernel<<<(131072+255)/256,256>>>(aaa_w2,   64, 1024,128,1024, W_L(5));
    wsplit_kernel<<<(131072+255)/256,256>>>(gate_w2,  128,1024,128,1024, W_L(6));
    wsplit_kernel<<<(131072+255)/256,256>>>(mv_w2,    32, 1024,128,1024, W_L(7));

    dim3 gBig(8, 128), gNar(1, 128);
    const long MH = (long)Mrows*128;

    // projections (variant order in g_XH: 0 r,1 w,2 k,3 v,4 a,5 g)
    gemm_bf16<<<gBig,256,SMEM_TOT>>>(pXH+0l*BTC, pXL+0l*BTC, pWH+W_R, pWL+W_R,
        1024, 1024, 0, nullptr, 0, pR, nullptr, nullptr, nullptr);
    gemm_bf16<<<gBig,256,SMEM_TOT>>>(pXH+2l*BTC, pXL+2l*BTC, pWH+W_K, pWL+W_K,
        1024, 1024, 0, nullptr, 0, pK, nullptr, nullptr, nullptr);
    gemm_bf16<<<gBig,256,SMEM_TOT>>>(pXH+3l*BTC, pXL+3l*BTC, pWH+W_V, pWL+W_V,
        1024, 1024, 0, nullptr, 0, pV, nullptr, nullptr, nullptr);

    // LoRA stage-1 -> bf16 hi/lo hidden states
    gemm_bf16<<<gNar,256,SMEM_TOT>>>(pXH+1l*BTC, pXL+1l*BTC, pWH+W_L(0), pWL+W_L(0),
        128, 1024, 4, nullptr, 1, nullptr, pHH+0*MH, pHL+0*MH, nullptr);
    gemm_bf16<<<gNar,256,SMEM_TOT>>>(pXH+4l*BTC, pXL+4l*BTC, pWH+W_L(1), pWL+W_L(1),
        128, 1024, 0, nullptr, 1, nullptr, pHH+1*MH, pHL+1*MH, nullptr);
    gemm_bf16<<<gNar,256,SMEM_TOT>>>(pXH+5l*BTC, pXL+5l*BTC, pWH+W_L(2), pWL+W_L(2),
        128, 1024, 5, nullptr, 1, nullptr, pHH+2*MH, pHL+2*MH, nullptr);
    gemm_bf16<<<gNar,256,SMEM_TOT>>>(pXH+3l*BTC, pXL+3l*BTC, pWH+W_L(3), pWL+W_L(3),
        128, 1024, 0, nullptr, 1, nullptr, pHH+3*MH, pHL+3*MH, nullptr);

    // LoRA stage-2 (K padded to 128)
    gemm_bf16<<<gBig,256,SMEM_TOT>>>(pHH+0*MH, pHL+0*MH, pWH+W_L(4), pWL+W_L(4),
        1024, 128, 1, tdecay, 0, pWD, nullptr, nullptr, nullptr);
    gemm_bf16<<<gBig,256,SMEM_TOT>>>(pHH+1*MH, pHL+1*MH, pWH+W_L(5), pWL+W_L(5),
        1024, 128, 2, taaaaa, 0, pA, nullptr, nullptr, nullptr);
    gemm_bf16<<<gBig,256,SMEM_TOT>>>(pHH+2*MH, pHL+2*MH, pWH+W_L(6), pWL+W_L(6),
        1024, 128, 0, nullptr, 0, pG, nullptr, nullptr, nullptr);
    gemm_bf16<<<gBig,256,SMEM_TOT>>>(pHH+3*MH, pHL+3*MH, pWH+W_L(7), pWL+W_L(7),
        1024, 128, 3, misc_v, 0, pV, nullptr, nullptr, v0);

    // kk normalize + k update
    kk_kernel<<<(Bb*Tt*Hh)/8, 256>>>(pK, pA, misc_kkk, misc_a, pKK, pK);

    // sequential recurrence
    scan_kernel<<<Bb*Hh, 128>>>(pR, pWD, pK, pV, pKK, pA, pY);

    // groupnorm + bonus + gate -> bf16 planes
    post_kernel<<<(Bb*Tt*Hh)/8, 256>>>(pY, pR, pK, pV, pG, faaaa, ln_w, ln_b);

    // output projection
    gemm_bf16<<<gBig,256,SMEM_TOT>>>(pYGH, pYGL, pWH+W_O, pWL+W_O,
        1024, 1024, 0, nullptr, 0, (float*)d_out, nullptr, nullptr, nullptr);

    if (out_size >= 2*BTC)
        copy_kernel<<<(BTC/4 + 255)/256, 256>>>(v0, (float*)d_out + BTC, BTC/4);
}